// round 5
// baseline (speedup 1.0000x reference)
#include <cuda_runtime.h>
#include <cuda_fp16.h>

// bg : (1, 4, 32, 32, 32, 16) f32   bilateral grid (c, h, w, d, up)
// gm : (1, 1, 128, 128, 128) f32    guidance
// out: (1, 4, 128, 128, 128) f32
//
// Block = 4x4 (gh,gw) tile x 128 gd, 512 threads.
// Stage 3x3 coarse planes as fp16 z-PAIRS: pr[plane][t][z] = {c0..3@z, c0..3@z+1}.
// Bank-quad = (t*32+z) mod 8 = z mod 8  ->  random t cannot conflict.
// Lanes take gd strided by 4 so z is lane-distinct -> conflict-free LDS.128.

#define GH 128
#define GW 128
#define GD 128
#define HH 32
#define WW 32
#define DD 32
#define UPD 16
#define NVOX (GH * GW * GD)
#define CH_STRIDE (HH * WW * DD * UPD)

#define TH 4
#define TW 4
#define NX 3
#define NY 3
#define NP (NX * NY)                       // 9 planes

#define PR_UNITS (NP * UPD * DD)           // uint4 cells: 4608
#define PR_BYTES (PR_UNITS * 16)           // 73728
#define SCR_UNITS (NP * DD * 17)           // uint2 cells, padded t-rows: 4896
#define SCR_BYTES (SCR_UNITS * 8)          // 39168
#define SMEM_BYTES (PR_BYTES + SCR_BYTES)  // 112896

__global__ __launch_bounds__(512) void bgrid_slice_kernel(
    const float* __restrict__ bg,
    const float* __restrict__ gm,
    float* __restrict__ out)
{
    extern __shared__ char smraw[];
    uint4* __restrict__ pr  = (uint4*)smraw;               // [p][t][z]
    uint2* __restrict__ scr = (uint2*)(smraw + PR_BYTES);  // [p][z][t] pad17

    const float s = 31.0f / 127.0f;
    const int tid = threadIdx.x;
    const int gh0 = blockIdx.y * TH;
    const int gw0 = blockIdx.x * TW;

    const int x0base = (int)floorf((float)gh0 * s);
    const int y0base = (int)floorf((float)gw0 * s);

    // ---- Phase A: coalesced LDG -> scratch (fp16, [p][z][t], row pad 17) ----
    {
        const int tt = tid & 15;           // 0..15
        const int z  = tid >> 4;           // 0..31
#pragma unroll
        for (int p = 0; p < NP; p++) {
            const int gx = min(x0base + p / NY, HH - 1);
            const int gy = min(y0base + p % NY, WW - 1);
            const int gbase = (((gx * WW) + gy) * DD + z) * UPD + tt;
            float c0 = __ldg(bg + 0 * CH_STRIDE + gbase);
            float c1 = __ldg(bg + 1 * CH_STRIDE + gbase);
            float c2 = __ldg(bg + 2 * CH_STRIDE + gbase);
            float c3 = __ldg(bg + 3 * CH_STRIDE + gbase);
            __half2 h01 = __floats2half2_rn(c0, c1);
            __half2 h23 = __floats2half2_rn(c2, c3);
            uint2 v;
            v.x = *(const unsigned int*)&h01;
            v.y = *(const unsigned int*)&h23;
            scr[(p * DD + z) * 17 + tt] = v;
        }
    }
    __syncthreads();

    // ---- Phase B: scratch -> z-pair layout pr[p][t][z] ----
    {
        const int z  = tid & 31;           // 0..31
        const int t  = tid >> 5;           // 0..15
        const int z1 = min(z + 1, DD - 1);
#pragma unroll
        for (int p = 0; p < NP; p++) {
            uint2 a = scr[(p * DD + z) * 17 + t];
            uint2 b = scr[(p * DD + z1) * 17 + t];
            pr[(p * UPD + t) * DD + z] = make_uint4(a.x, a.y, b.x, b.y);
        }
    }
    __syncthreads();

    // ---- Phase 2: interpolate. gd strided by 4 across lanes. ----
    const int w    = tid >> 5;             // warp 0..15
    const int lane = tid & 31;
    const int lgw  = w >> 2;               // 0..3
    const int q    = w & 3;                // 0..3
    const int gd   = lane * 4 + q;         // 0..127, lane-strided
    const int gw   = gw0 + lgw;

    // y (per gw)
    float yv = (float)gw * s;
    float yf = floorf(yv);
    float fy = yv - yf;
    int   y0i = (int)yf;
    const int yi_[2] = { y0i - y0base, min(y0i + 1, WW - 1) - y0base };
    const float wy_[2] = { 1.0f - fy, fy };

    // z (per gd)
    float zv = (float)gd * s;
    float zf = floorf(zv);
    float fz = zv - zf;
    int   iz0 = (int)zf;                   // pair cell handles z+1 clamp
    const float wzA = 1.0f - fz, wzB = fz;

    // prefetch guidance (MLP)
    float tval[TH];
#pragma unroll
    for (int i = 0; i < TH; i++)
        tval[i] = __ldg(gm + ((gh0 + i) * GW + gw) * GD + gd) * 15.0f;

#pragma unroll
    for (int i = 0; i < TH; i++) {
        const int gh = gh0 + i;
        float xv = (float)gh * s;
        float xf = floorf(xv);
        float fx = xv - xf;
        int   x0i = (int)xf;
        const int xi_[2] = { x0i - x0base, min(x0i + 1, HH - 1) - x0base };
        const float wx_[2] = { 1.0f - fx, fx };

        float t = fminf(fmaxf(tval[i], 0.0f), 15.0f);
        int   t0 = min((int)t, UPD - 2);
        float ft = t - (float)t0;
        const int t1 = t0 + 1;
        const float ftA = 1.0f - ft;

        // per-voxel (z,t) weight quad
        const float q00 = ftA * wzA;   // (z0, t0)
        const float q01 = ftA * wzB;   // (z1, t0)
        const float q10 = ft  * wzA;   // (z0, t1)
        const float q11 = ft  * wzB;   // (z1, t1)

        float a0 = 0.0f, a1 = 0.0f, a2 = 0.0f, a3 = 0.0f;

#pragma unroll
        for (int cx = 0; cx < 2; cx++) {
#pragma unroll
            for (int cy = 0; cy < 2; cy++) {
                const int p = xi_[cx] * NY + yi_[cy];
                const float wxy = wx_[cx] * wy_[cy];
                const int base = (p * UPD) * DD + iz0;
                uint4 ua = pr[base + t0 * DD];   // {c01@z0,c23@z0,c01@z1,c23@z1} @t0
                uint4 ub = pr[base + t1 * DD];   // same @t1

                const float w00 = wxy * q00;
                const float w01 = wxy * q01;
                const float w10 = wxy * q10;
                const float w11 = wxy * q11;

                float2 az0_01 = __half22float2(*(const __half2*)&ua.x);
                float2 az0_23 = __half22float2(*(const __half2*)&ua.y);
                float2 az1_01 = __half22float2(*(const __half2*)&ua.z);
                float2 az1_23 = __half22float2(*(const __half2*)&ua.w);
                float2 bz0_01 = __half22float2(*(const __half2*)&ub.x);
                float2 bz0_23 = __half22float2(*(const __half2*)&ub.y);
                float2 bz1_01 = __half22float2(*(const __half2*)&ub.z);
                float2 bz1_23 = __half22float2(*(const __half2*)&ub.w);

                a0 = fmaf(w00, az0_01.x, a0); a0 = fmaf(w01, az1_01.x, a0);
                a0 = fmaf(w10, bz0_01.x, a0); a0 = fmaf(w11, bz1_01.x, a0);
                a1 = fmaf(w00, az0_01.y, a1); a1 = fmaf(w01, az1_01.y, a1);
                a1 = fmaf(w10, bz0_01.y, a1); a1 = fmaf(w11, bz1_01.y, a1);
                a2 = fmaf(w00, az0_23.x, a2); a2 = fmaf(w01, az1_23.x, a2);
                a2 = fmaf(w10, bz0_23.x, a2); a2 = fmaf(w11, bz1_23.x, a2);
                a3 = fmaf(w00, az0_23.y, a3); a3 = fmaf(w01, az1_23.y, a3);
                a3 = fmaf(w10, bz0_23.y, a3); a3 = fmaf(w11, bz1_23.y, a3);
            }
        }

        const int oidx = (gh * GW + gw) * GD + gd;
        out[0 * NVOX + oidx] = a0;
        out[1 * NVOX + oidx] = a1;
        out[2 * NVOX + oidx] = a2;
        out[3 * NVOX + oidx] = a3;
    }
}

extern "C" void kernel_launch(void* const* d_in, const int* in_sizes, int n_in,
                              void* d_out, int out_size)
{
    const float* bg = (const float*)d_in[0];
    const float* gm = (const float*)d_in[1];
    float* out = (float*)d_out;

    cudaFuncSetAttribute(bgrid_slice_kernel,
                         cudaFuncAttributeMaxDynamicSharedMemorySize,
                         SMEM_BYTES);

    dim3 grid(GW / TW, GH / TH);
    bgrid_slice_kernel<<<grid, 512, SMEM_BYTES>>>(bg, gm, out);
}

// round 6
// speedup vs baseline: 1.2129x; 1.2129x over previous
#include <cuda_runtime.h>
#include <cuda_fp16.h>

// bg : (1, 4, 32, 32, 32, 16) f32   bilateral grid (c, h, w, d, up)
// gm : (1, 1, 128, 128, 128) f32    guidance
// out: (1, 4, 128, 128, 128) f32
//
// Block = 4x4 (gh,gw) tile x 128 gd, 512 threads.
// Stage 3x3 coarse planes as fp16 z-PAIRS: pr[p][t][z] = {c0..3@z, c0..3@z+1}.
// Phase 2: one warp per (gh,gw) column; each lane owns 4 consecutive gd.
//   -> float4 gm load, float4 out stores (coalesced), AND conflict-free
//      LDS.128 (z ~ lane, distinct mod 8), with 4-voxel ILP per lane.

#define GH 128
#define GW 128
#define GD 128
#define HH 32
#define WW 32
#define DD 32
#define UPD 16
#define NVOX (GH * GW * GD)
#define CH_STRIDE (HH * WW * DD * UPD)

#define TH 4
#define TW 4
#define NX 3
#define NY 3
#define NP (NX * NY)                       // 9 planes

#define PR_UNITS (NP * UPD * DD)           // uint4 cells: 4608
#define PR_BYTES (PR_UNITS * 16)           // 73728
#define SCR_UNITS (NP * DD * 17)           // uint2 cells, padded t-rows
#define SCR_BYTES (SCR_UNITS * 8)          // 39168
#define SMEM_BYTES (PR_BYTES + SCR_BYTES)  // 112896

__global__ __launch_bounds__(512) void bgrid_slice_kernel(
    const float* __restrict__ bg,
    const float* __restrict__ gm,
    float* __restrict__ out)
{
    extern __shared__ char smraw[];
    uint4* __restrict__ pr  = (uint4*)smraw;               // [p][t][z]
    uint2* __restrict__ scr = (uint2*)(smraw + PR_BYTES);  // [p][z][t] pad17

    const float s = 31.0f / 127.0f;
    const int tid = threadIdx.x;
    const int gh0 = blockIdx.y * TH;
    const int gw0 = blockIdx.x * TW;

    const int x0base = (int)floorf((float)gh0 * s);
    const int y0base = (int)floorf((float)gw0 * s);

    // ---- Phase A: coalesced LDG -> scratch (fp16, [p][z][t], row pad 17) ----
    {
        const int tt = tid & 15;           // 0..15
        const int z  = tid >> 4;           // 0..31
#pragma unroll
        for (int p = 0; p < NP; p++) {
            const int gx = min(x0base + p / NY, HH - 1);
            const int gy = min(y0base + p % NY, WW - 1);
            const int gbase = (((gx * WW) + gy) * DD + z) * UPD + tt;
            float c0 = __ldg(bg + 0 * CH_STRIDE + gbase);
            float c1 = __ldg(bg + 1 * CH_STRIDE + gbase);
            float c2 = __ldg(bg + 2 * CH_STRIDE + gbase);
            float c3 = __ldg(bg + 3 * CH_STRIDE + gbase);
            __half2 h01 = __floats2half2_rn(c0, c1);
            __half2 h23 = __floats2half2_rn(c2, c3);
            uint2 v;
            v.x = *(const unsigned int*)&h01;
            v.y = *(const unsigned int*)&h23;
            scr[(p * DD + z) * 17 + tt] = v;
        }
    }
    __syncthreads();

    // ---- Phase B: scratch -> z-pair layout pr[p][t][z] ----
    {
        const int z  = tid & 31;           // 0..31
        const int t  = tid >> 5;           // 0..15
        const int z1 = min(z + 1, DD - 1);
#pragma unroll
        for (int p = 0; p < NP; p++) {
            uint2 a = scr[(p * DD + z) * 17 + t];
            uint2 b = scr[(p * DD + z1) * 17 + t];
            pr[(p * UPD + t) * DD + z] = make_uint4(a.x, a.y, b.x, b.y);
        }
    }
    __syncthreads();

    // ---- Phase 2: one warp per column; lane owns gd = lane*4 .. lane*4+3 ----
    const int w    = tid >> 5;             // 0..15
    const int lane = tid & 31;
    const int gh   = gh0 + (w >> 2);
    const int gw   = gw0 + (w & 3);
    const int gdb  = lane * 4;

    // x weights (per warp)
    float xv = (float)gh * s;
    float xf = floorf(xv);
    float fx = xv - xf;
    int   x0i = (int)xf;
    const int xi_[2] = { x0i - x0base, min(x0i + 1, HH - 1) - x0base };
    const float wx_[2] = { 1.0f - fx, fx };

    // y weights (per warp)
    float yv = (float)gw * s;
    float yf = floorf(yv);
    float fy = yv - yf;
    int   y0i = (int)yf;
    const int yi_[2] = { y0i - y0base, min(y0i + 1, WW - 1) - y0base };
    const float wy_[2] = { 1.0f - fy, fy };

    // guidance: one float4 per lane (coalesced)
    const int colbase = (gh * GW + gw) * GD;
    float4 g = *(const float4*)(gm + colbase + gdb);
    float tv[4] = { g.x, g.y, g.z, g.w };

    // per-voxel z / t params
    int   izofs[4];     // iz0 (pair cell handles z+1 clamp)
    int   t0_[4], t1_[4];
    float q00[4], q01[4], q10[4], q11[4];
#pragma unroll
    for (int j = 0; j < 4; j++) {
        const int gd = gdb + j;
        float zv = (float)gd * s;
        float zf = floorf(zv);
        float fz = zv - zf;
        izofs[j] = (int)zf;
        float t = fminf(fmaxf(tv[j] * 15.0f, 0.0f), 15.0f);
        int   t0 = min((int)t, UPD - 2);
        float ft = t - (float)t0;
        t0_[j] = t0;
        t1_[j] = t0 + 1;
        const float ftA = 1.0f - ft;
        const float wzA = 1.0f - fz, wzB = fz;
        q00[j] = ftA * wzA;
        q01[j] = ftA * wzB;
        q10[j] = ft  * wzA;
        q11[j] = ft  * wzB;
    }

    float a0[4] = {0,0,0,0}, a1[4] = {0,0,0,0};
    float a2[4] = {0,0,0,0}, a3[4] = {0,0,0,0};

#pragma unroll
    for (int cx = 0; cx < 2; cx++) {
#pragma unroll
        for (int cy = 0; cy < 2; cy++) {
            const int p = xi_[cx] * NY + yi_[cy];
            const float wxy = wx_[cx] * wy_[cy];
            const int pb = p * UPD * DD;

            uint4 ua[4], ub[4];
#pragma unroll
            for (int j = 0; j < 4; j++) {
                const int base = pb + izofs[j];
                ua[j] = pr[base + t0_[j] * DD];   // {c01@z0,c23@z0,c01@z1,c23@z1} @t0
                ub[j] = pr[base + t1_[j] * DD];   // same @t1
            }
#pragma unroll
            for (int j = 0; j < 4; j++) {
                const float w00 = wxy * q00[j];
                const float w01 = wxy * q01[j];
                const float w10 = wxy * q10[j];
                const float w11 = wxy * q11[j];

                float2 az0_01 = __half22float2(*(const __half2*)&ua[j].x);
                float2 az0_23 = __half22float2(*(const __half2*)&ua[j].y);
                float2 az1_01 = __half22float2(*(const __half2*)&ua[j].z);
                float2 az1_23 = __half22float2(*(const __half2*)&ua[j].w);
                float2 bz0_01 = __half22float2(*(const __half2*)&ub[j].x);
                float2 bz0_23 = __half22float2(*(const __half2*)&ub[j].y);
                float2 bz1_01 = __half22float2(*(const __half2*)&ub[j].z);
                float2 bz1_23 = __half22float2(*(const __half2*)&ub[j].w);

                a0[j] = fmaf(w00, az0_01.x, a0[j]); a0[j] = fmaf(w01, az1_01.x, a0[j]);
                a0[j] = fmaf(w10, bz0_01.x, a0[j]); a0[j] = fmaf(w11, bz1_01.x, a0[j]);
                a1[j] = fmaf(w00, az0_01.y, a1[j]); a1[j] = fmaf(w01, az1_01.y, a1[j]);
                a1[j] = fmaf(w10, bz0_01.y, a1[j]); a1[j] = fmaf(w11, bz1_01.y, a1[j]);
                a2[j] = fmaf(w00, az0_23.x, a2[j]); a2[j] = fmaf(w01, az1_23.x, a2[j]);
                a2[j] = fmaf(w10, bz0_23.x, a2[j]); a2[j] = fmaf(w11, bz1_23.x, a2[j]);
                a3[j] = fmaf(w00, az0_23.y, a3[j]); a3[j] = fmaf(w01, az1_23.y, a3[j]);
                a3[j] = fmaf(w10, bz0_23.y, a3[j]); a3[j] = fmaf(w11, bz1_23.y, a3[j]);
            }
        }
    }

    // coalesced float4 stores per channel
    *(float4*)(out + 0 * NVOX + colbase + gdb) = make_float4(a0[0], a0[1], a0[2], a0[3]);
    *(float4*)(out + 1 * NVOX + colbase + gdb) = make_float4(a1[0], a1[1], a1[2], a1[3]);
    *(float4*)(out + 2 * NVOX + colbase + gdb) = make_float4(a2[0], a2[1], a2[2], a2[3]);
    *(float4*)(out + 3 * NVOX + colbase + gdb) = make_float4(a3[0], a3[1], a3[2], a3[3]);
}

extern "C" void kernel_launch(void* const* d_in, const int* in_sizes, int n_in,
                              void* d_out, int out_size)
{
    const float* bg = (const float*)d_in[0];
    const float* gm = (const float*)d_in[1];
    float* out = (float*)d_out;

    cudaFuncSetAttribute(bgrid_slice_kernel,
                         cudaFuncAttributeMaxDynamicSharedMemorySize,
                         SMEM_BYTES);

    dim3 grid(GW / TW, GH / TH);
    bgrid_slice_kernel<<<grid, 512, SMEM_BYTES>>>(bg, gm, out);
}

// round 7
// speedup vs baseline: 1.3077x; 1.0781x over previous
#include <cuda_runtime.h>
#include <cuda_fp16.h>

// bg : (1, 4, 32, 32, 32, 16) f32   bilateral grid (c, h, w, d, up)
// gm : (1, 1, 128, 128, 128) f32    guidance
// out: (1, 4, 128, 128, 128) f32
//
// Block = 4x4 (gh,gw) tile x 128 gd, 512 threads, 3 blocks/SM.
// pr[p][t][z] = 8B fp16 cell {c01,c23}.  bank-pair = z mod 16 -> random t
// cannot conflict; phase-2 lanes carry distinct z -> conflict-free LDS.64.
// Staging: coalesced LDG -> small padded scratch (3 planes) -> pr transpose.

#define GH 128
#define GW 128
#define GD 128
#define HH 32
#define WW 32
#define DD 32
#define UPD 16
#define NVOX (GH * GW * GD)
#define CH_STRIDE (HH * WW * DD * UPD)

#define TH 4
#define TW 4
#define NX 3
#define NY 3
#define NP (NX * NY)                       // 9 planes
#define PCHUNK 3                           // planes staged per chunk

#define PR_CELLS (NP * UPD * DD)           // uint2 cells: 4608
#define PR_BYTES (PR_CELLS * 8)            // 36864
#define SCR_CELLS (PCHUNK * DD * 17)       // uint2 cells, padded t-rows: 1632
#define SCR_BYTES (SCR_CELLS * 8)          // 13056
#define SMEM_BYTES (PR_BYTES + SCR_BYTES)  // 49920

__global__ __launch_bounds__(512, 3) void bgrid_slice_kernel(
    const float* __restrict__ bg,
    const float* __restrict__ gm,
    float* __restrict__ out)
{
    extern __shared__ char smraw[];
    uint2* __restrict__ pr  = (uint2*)smraw;               // [p][t][z]
    uint2* __restrict__ scr = (uint2*)(smraw + PR_BYTES);  // [pc][z][t] pad17

    const float s = 31.0f / 127.0f;
    const int tid = threadIdx.x;
    const int gh0 = blockIdx.y * TH;
    const int gw0 = blockIdx.x * TW;

    const int x0base = (int)floorf((float)gh0 * s);
    const int y0base = (int)floorf((float)gw0 * s);

    // phase-2 identity (needed early for gm prefetch)
    const int w    = tid >> 5;             // warp 0..15
    const int lane = tid & 31;
    const int gh   = gh0 + (w >> 2);
    const int gw   = gw0 + (w & 3);
    const int gdb  = lane * 4;
    const int colbase = (gh * GW + gw) * GD;

    // guidance in flight during staging (coalesced float4)
    const float4 g = *(const float4*)(gm + colbase + gdb);

    // ---- Staging: 3 chunks of 3 planes --------------------------------
    {
        const int tt = tid & 15;           // 0..15 (phase A)
        const int za = tid >> 4;           // 0..31 (phase A)
        const int zb = tid & 31;           // 0..31 (phase B)
        const int tb = tid >> 5;           // 0..15 (phase B)
#pragma unroll
        for (int c = 0; c < NP / PCHUNK; c++) {
            // A: coalesced LDG -> scr (fp16, [pc][z][t] pad 17)
#pragma unroll
            for (int i = 0; i < PCHUNK; i++) {
                const int p  = c * PCHUNK + i;
                const int gx = min(x0base + p / NY, HH - 1);
                const int gy = min(y0base + p % NY, WW - 1);
                const int gbase = (((gx * WW) + gy) * DD + za) * UPD + tt;
                float c0 = __ldg(bg + 0 * CH_STRIDE + gbase);
                float c1 = __ldg(bg + 1 * CH_STRIDE + gbase);
                float c2 = __ldg(bg + 2 * CH_STRIDE + gbase);
                float c3 = __ldg(bg + 3 * CH_STRIDE + gbase);
                __half2 h01 = __floats2half2_rn(c0, c1);
                __half2 h23 = __floats2half2_rn(c2, c3);
                uint2 v;
                v.x = *(const unsigned int*)&h01;
                v.y = *(const unsigned int*)&h23;
                scr[(i * DD + za) * 17 + tt] = v;
            }
            __syncthreads();
            // B: scr -> pr[p][t][z]  (lanes vary z: conflict-free both sides)
#pragma unroll
            for (int i = 0; i < PCHUNK; i++) {
                const int p = c * PCHUNK + i;
                pr[(p * UPD + tb) * DD + zb] = scr[(i * DD + zb) * 17 + tb];
            }
            __syncthreads();
        }
    }

    // ---- Phase 2: one warp per column; lane owns gd = lane*4 .. +3 ----
    // x weights (per warp)
    float xv = (float)gh * s;
    float xf = floorf(xv);
    float fx = xv - xf;
    int   x0i = (int)xf;
    const int xi_[2] = { x0i - x0base, min(x0i + 1, HH - 1) - x0base };
    const float wx_[2] = { 1.0f - fx, fx };

    // y weights (per warp)
    float yv = (float)gw * s;
    float yf = floorf(yv);
    float fy = yv - yf;
    int   y0i = (int)yf;
    const int yi_[2] = { y0i - y0base, min(y0i + 1, WW - 1) - y0base };
    const float wy_[2] = { 1.0f - fy, fy };

    const float tv[4] = { g.x, g.y, g.z, g.w };

    // per-voxel cell offsets and (z,t) bilinear weights
    int   o00[4], dz[4];
    float q00[4], q01[4], q10[4], q11[4];
#pragma unroll
    for (int j = 0; j < 4; j++) {
        const int gd = gdb + j;
        float zv = (float)gd * s;
        float zf = floorf(zv);
        float fz = zv - zf;
        int   iz0 = (int)zf;
        int   iz1 = min(iz0 + 1, DD - 1);
        float t = fminf(fmaxf(tv[j] * 15.0f, 0.0f), 15.0f);
        int   t0 = min((int)t, UPD - 2);
        float ft = t - (float)t0;
        o00[j] = t0 * DD + iz0;            // (t0, z0) cell offset within plane
        dz[j]  = iz1 - iz0;                // 0 or 1
        const float ftA = 1.0f - ft;
        const float wzA = 1.0f - fz, wzB = fz;
        q00[j] = ftA * wzA;                // (z0,t0)
        q01[j] = ftA * wzB;                // (z1,t0)
        q10[j] = ft  * wzA;                // (z0,t1)
        q11[j] = ft  * wzB;                // (z1,t1)
    }

    float a0[4] = {0,0,0,0}, a1[4] = {0,0,0,0};
    float a2[4] = {0,0,0,0}, a3[4] = {0,0,0,0};

#pragma unroll
    for (int cx = 0; cx < 2; cx++) {
#pragma unroll
        for (int cy = 0; cy < 2; cy++) {
            const int p = xi_[cx] * NY + yi_[cy];
            const float wxy = wx_[cx] * wy_[cy];
            const uint2* __restrict__ pp = pr + p * (UPD * DD);

            uint2 u00[4], u01[4], u10[4], u11[4];
#pragma unroll
            for (int j = 0; j < 4; j++) {
                const int b = o00[j];
                u00[j] = pp[b];                 // (t0, z0)
                u01[j] = pp[b + dz[j]];         // (t0, z1)
                u10[j] = pp[b + DD];            // (t1, z0)
                u11[j] = pp[b + DD + dz[j]];    // (t1, z1)
            }
#pragma unroll
            for (int j = 0; j < 4; j++) {
                const float w00 = wxy * q00[j];
                const float w01 = wxy * q01[j];
                const float w10 = wxy * q10[j];
                const float w11 = wxy * q11[j];

                float2 v00a = __half22float2(*(const __half2*)&u00[j].x);
                float2 v00b = __half22float2(*(const __half2*)&u00[j].y);
                float2 v01a = __half22float2(*(const __half2*)&u01[j].x);
                float2 v01b = __half22float2(*(const __half2*)&u01[j].y);
                float2 v10a = __half22float2(*(const __half2*)&u10[j].x);
                float2 v10b = __half22float2(*(const __half2*)&u10[j].y);
                float2 v11a = __half22float2(*(const __half2*)&u11[j].x);
                float2 v11b = __half22float2(*(const __half2*)&u11[j].y);

                a0[j] = fmaf(w00, v00a.x, a0[j]); a0[j] = fmaf(w01, v01a.x, a0[j]);
                a0[j] = fmaf(w10, v10a.x, a0[j]); a0[j] = fmaf(w11, v11a.x, a0[j]);
                a1[j] = fmaf(w00, v00a.y, a1[j]); a1[j] = fmaf(w01, v01a.y, a1[j]);
                a1[j] = fmaf(w10, v10a.y, a1[j]); a1[j] = fmaf(w11, v11a.y, a1[j]);
                a2[j] = fmaf(w00, v00b.x, a2[j]); a2[j] = fmaf(w01, v01b.x, a2[j]);
                a2[j] = fmaf(w10, v10b.x, a2[j]); a2[j] = fmaf(w11, v11b.x, a2[j]);
                a3[j] = fmaf(w00, v00b.y, a3[j]); a3[j] = fmaf(w01, v01b.y, a3[j]);
                a3[j] = fmaf(w10, v10b.y, a3[j]); a3[j] = fmaf(w11, v11b.y, a3[j]);
            }
        }
    }

    // coalesced float4 stores per channel
    *(float4*)(out + 0 * NVOX + colbase + gdb) = make_float4(a0[0], a0[1], a0[2], a0[3]);
    *(float4*)(out + 1 * NVOX + colbase + gdb) = make_float4(a1[0], a1[1], a1[2], a1[3]);
    *(float4*)(out + 2 * NVOX + colbase + gdb) = make_float4(a2[0], a2[1], a2[2], a2[3]);
    *(float4*)(out + 3 * NVOX + colbase + gdb) = make_float4(a3[0], a3[1], a3[2], a3[3]);
}

extern "C" void kernel_launch(void* const* d_in, const int* in_sizes, int n_in,
                              void* d_out, int out_size)
{
    const float* bg = (const float*)d_in[0];
    const float* gm = (const float*)d_in[1];
    float* out = (float*)d_out;

    cudaFuncSetAttribute(bgrid_slice_kernel,
                         cudaFuncAttributeMaxDynamicSharedMemorySize,
                         SMEM_BYTES);

    dim3 grid(GW / TW, GH / TH);
    bgrid_slice_kernel<<<grid, 512, SMEM_BYTES>>>(bg, gm, out);
}